// round 2
// baseline (speedup 1.0000x reference)
#include <cuda_runtime.h>
#include <math.h>

typedef unsigned long long u64;

#define NIMG 16
#define NO   192
#define Hh   160
#define Wd   160
#define HW   25600
#define PAD  34

// win3: kh=54, khkw=2916, P=9 ; win5: kh=32, khkw=1024, P=25
#define KHKW3 2916
#define P3    9
#define A3    26244      // khkw3*P3
#define B3    186624     // 64*khkw3
#define U3IMG 1679616    // 64*khkw3*P3
#define KHKW5 1024
#define P5    25
#define A5    25600
#define B5    65536
#define U5IMG 1638400
#define NPI   560        // 16 + 144 + 400 pseudo-images

// ---------------- scratch ----------------
__device__ float g_ex[(size_t)NIMG*NO*HW];     // 315MB
__device__ float g_u3[(size_t)NIMG*U3IMG];     // 107MB
__device__ float g_u5[(size_t)NIMG*U5IMG];     // 105MB
__device__ float g_sf1[NIMG*HW];
__device__ float g_sf3[NIMG*P3*KHKW3];
__device__ float g_sf5[NIMG*P5*KHKW5];
__device__ float g_Z[NPI], g_S[NPI*64], g_Pm[NPI*64];
__device__ float g_gt[NPI*64], g_veff[NPI*64], g_beff[NPI];
__device__ float g_W2t[NO*64], g_Ft[64*64], g_vb[64], g_expWt[64*NO];

// ---------------- helpers ----------------
__device__ __forceinline__ u64 pk2(float lo, float hi){
    u64 r; asm("mov.b64 %0,{%1,%2};":"=l"(r):"f"(lo),"f"(hi)); return r;
}
__device__ __forceinline__ void fma2(u64 &d, u64 a, u64 b){
    asm("fma.rn.f32x2 %0,%1,%2,%3;":"=l"(d):"l"(a),"l"(b),"l"(d));
}
__device__ __forceinline__ float2 up2(u64 v){
    float2 f; asm("mov.b64 {%0,%1},%2;":"=f"(f.x),"=f"(f.y):"l"(v)); return f;
}
__device__ __forceinline__ float sigf(float x){ return 1.f/(1.f+expf(-x)); }
__device__ __forceinline__ int cover3(int h, int* r){
    int n=0;
    #pragma unroll
    for(int i=0;i<3;i++){ int lo=53*i; if(h>=lo && h<=lo+53) r[n++]=i; }
    return n;
}

// ================ K0a: zero accumulators ================
__global__ void k_zero(){
    int i = blockIdx.x*256 + threadIdx.x;
    if(i < NPI) g_Z[i]=0.f;
    if(i < NPI*64){ g_S[i]=0.f; g_Pm[i]=0.f; }
}

// ================ K0b: weight prep ================
__global__ void k_wprep(const float* __restrict__ exp_w, const float* __restrict__ res_w,
                        const float* __restrict__ res_b, const float* __restrict__ fus_w,
                        const float* __restrict__ fus_b){
    int t = threadIdx.x;
    for(int i=t;i<64*NO;i+=256){ int c=i/NO, o=i%NO; g_expWt[i]=exp_w[o*64+c]; }
    for(int i=t;i<64*64;i+=256){ int c=i/64, o=i%64; g_Ft[i]=fus_w[o*64+c]; }
    for(int i=t;i<NO*64;i+=256){
        int k=i/64, o=i%64; float s=0.f;
        for(int c=0;c<64;c++) s += fus_w[o*64+c]*res_w[c*NO+k];
        g_W2t[i]=s;
    }
    for(int o=t;o<64;o+=256){
        float s=fus_b[o];
        for(int c=0;c<64;c++) s += fus_w[o*64+c]*res_b[c];
        g_vb[o]=s;
    }
}

// ================ K1: ex = Wexp @ x ================
__global__ void __launch_bounds__(256) k1(const float* __restrict__ x,
                                          const float* __restrict__ exp_b){
    __shared__ __align__(16) float xs[64*PAD];
    int t = threadIdx.x;
    int wt = blockIdx.x, h = blockIdx.y, n = blockIdx.z;
    int w0 = wt*32;

    const float* xp = x + (size_t)n*64*HW + (size_t)h*Wd + w0;
    for(int i=t;i<64*32;i+=256){ int c=i>>5, pix=i&31; xs[c*PAD+pix]=xp[(size_t)c*HW+pix]; }
    __syncthreads();

    int ob = t&63, pg = t>>6, pb = pg*8;
    u64 acc[3][4];
    #pragma unroll
    for(int a=0;a<3;a++)
        #pragma unroll
        for(int j=0;j<4;j++) acc[a][j]=0ull;
    for(int c=0;c<64;c++){
        u64 xv[4];
        #pragma unroll
        for(int j=0;j<4;j++) xv[j]=*(const u64*)&xs[c*PAD+pb+j*2];
        #pragma unroll
        for(int a=0;a<3;a++){
            float w = g_expWt[c*NO + ob + a*64];
            u64 wp = pk2(w,w);
            #pragma unroll
            for(int j=0;j<4;j++) fma2(acc[a][j], wp, xv[j]);
        }
    }
    float* exg = g_ex + (size_t)n*NO*HW + (size_t)h*Wd + w0;
    #pragma unroll
    for(int a=0;a<3;a++){
        float b = exp_b[ob+a*64];
        #pragma unroll
        for(int j=0;j<4;j++){
            float2 v = up2(acc[a][j]);
            exg[(size_t)(ob+a*64)*HW + pb + j*2    ] = v.x + b;
            exg[(size_t)(ob+a*64)*HW + pb + j*2 + 1] = v.y + b;
        }
    }
}

// ================ K2: repack into unfold order ================
// win5: block (y, ci, n); u5[n][(ci*1024+y*32+x)*25 + p] = ex[n][128+ci][(p/5)*32+y][(p%5)*32+x]
__global__ void __launch_bounds__(256) k2_5(){
    __shared__ float rb[5*160];
    int y=blockIdx.x, ci=blockIdx.y, n=blockIdx.z;
    const float* exg = g_ex + (size_t)n*NO*HW + (size_t)(128+ci)*HW;
    for(int i=threadIdx.x;i<800;i+=256){ int ph=i/160, w=i%160; rb[i]=exg[(size_t)(ph*32+y)*Wd + w]; }
    __syncthreads();
    float* up = g_u5 + (size_t)n*U5IMG + (size_t)(ci*1024 + y*32)*25;
    for(int j=threadIdx.x;j<800;j+=256){
        int xx=j/25, p=j%25, ph=p/5, pw=p%5;
        up[j] = rb[ph*160 + pw*32 + xx];
    }
}
// win3: block (y in [0,54), ci, n)
__global__ void __launch_bounds__(256) k2_3(){
    __shared__ float rb[3*160];
    int y=blockIdx.x, ci=blockIdx.y, n=blockIdx.z;
    const float* exg = g_ex + (size_t)n*NO*HW + (size_t)(64+ci)*HW;
    for(int i=threadIdx.x;i<480;i+=256){ int ph=i/160, w=i%160; rb[i]=exg[(size_t)(53*ph+y)*Wd + w]; }
    __syncthreads();
    float* up = g_u3 + (size_t)n*U3IMG + (size_t)(ci*KHKW3 + y*54)*9;
    for(int j=threadIdx.x;j<486;j+=256){
        int xx=j/9, p=j%9, ph=p/3, pw=p%3;
        up[j] = rb[ph*160 + 53*pw + xx];
    }
}

// ================ K3: pseudo-image stats (Z, S, Pm) ================
// grid: (qtiles, piPerImg, n)
__global__ void __launch_bounds__(256) k_stats(const float* __restrict__ ub, int khkw,
                                               size_t imgstride, int piBase,
                                               const float* __restrict__ wq,
                                               const float* __restrict__ wqb){
    __shared__ float Vs[64*65];
    __shared__ float part[4*64];
    __shared__ float es[64];
    int q0 = blockIdx.x*64, bp = blockIdx.y, n = blockIdx.z;
    int t = threadIdx.x;
    const float* base = ub + (size_t)n*imgstride + (size_t)bp*64*khkw + q0;
    int qlim = khkw - q0; if(qlim>64) qlim=64;

    for(int i=t;i<4096;i+=256){
        int c=i>>6, j=i&63;
        Vs[c*65+j] = (j<qlim) ? base[(size_t)c*khkw + j] : 0.f;
    }
    __syncthreads();
    { // qdot partials
        int j=t&63, cg=t>>6;
        float s=0.f;
        #pragma unroll 4
        for(int cc=cg*16; cc<cg*16+16; cc++) s += wq[cc]*Vs[cc*65+j];
        part[cg*64+j]=s;
    }
    __syncthreads();
    int pi = piBase + n*gridDim.y + bp;
    if(t<64){
        float qd = part[t]+part[64+t]+part[128+t]+part[192+t] + wqb[0];
        float e = (t<qlim) ? expf(qd) : 0.f;
        es[t]=e;
        float z=e;
        for(int off=16;off;off>>=1) z += __shfl_xor_sync(0xffffffffu,z,off);
        if((t&31)==0) atomicAdd(&g_Z[pi], z);
    }
    __syncthreads();
    { // S, Pm partials
        int c=t&63, jg=t>>6;
        float ss=0.f, pm=0.f;
        #pragma unroll 4
        for(int jj=jg*16; jj<jg*16+16; jj++){ float v=Vs[c*65+jj]; ss += v*es[jj]; pm += v; }
        atomicAdd(&g_S[pi*64+c], ss);
        atomicAdd(&g_Pm[pi*64+c], pm);
    }
}

// ================ K4: per-pseudo-image finalize ================
__global__ void __launch_bounds__(64) k4(const float* __restrict__ chwv_w, const float* __restrict__ chwv_b,
                                         const float* __restrict__ chwz_w, const float* __restrict__ chwz_b,
                                         const float* __restrict__ ln_g,  const float* __restrict__ ln_b,
                                         const float* __restrict__ spwq_w,const float* __restrict__ spwq_b,
                                         const float* __restrict__ spwv_w,const float* __restrict__ spwv_b){
    int p = blockIdx.x, t = threadIdx.x;
    float hw = (p<16) ? 25600.f : ((p<160) ? 2916.f : 1024.f);
    __shared__ float xbar[64], pmean[64], wz[32], red[64], swq[32];

    float Zinv = 1.f/g_Z[p];
    xbar[t]  = g_S[p*64+t]*Zinv;
    pmean[t] = g_Pm[p*64+t]/hw;
    __syncthreads();

    if(t<32){
        float s = chwv_b[t];
        for(int c=0;c<64;c++) s += chwv_w[t*64+c]*xbar[c];
        wz[t]=s;
    }
    __syncthreads();

    float z = chwz_b[t];
    for(int j=0;j<32;j++) z += chwz_w[t*32+j]*wz[j];

    red[t]=z; __syncthreads();
    for(int s=32;s>0;s>>=1){ if(t<s) red[t]+=red[t+s]; __syncthreads(); }
    float mu = red[0]*(1.f/64.f); __syncthreads();
    float d = z-mu;
    red[t]=d*d; __syncthreads();
    for(int s=32;s>0;s>>=1){ if(t<s) red[t]+=red[t+s]; __syncthreads(); }
    float var = red[0]*(1.f/64.f);

    float zn = d*rsqrtf(var+1e-5f)*ln_g[t] + ln_b[t];
    g_gt[p*64+t] = sigf(zn);
    __syncthreads();

    if(t<32){
        float s = spwq_b[t];
        for(int c=0;c<64;c++) s += spwq_w[t*64+c]*pmean[c];
        float m=s;
        for(int off=16;off;off>>=1) m=fmaxf(m,__shfl_xor_sync(0xffffffffu,m,off));
        float e=expf(s-m), sum=e;
        for(int off=16;off;off>>=1) sum+=__shfl_xor_sync(0xffffffffu,sum,off);
        swq[t]=e/sum;
    }
    __syncthreads();

    float v=0.f;
    for(int j=0;j<32;j++) v += swq[j]*spwv_w[j*64+t];
    g_veff[p*64+t]=v;
    if(t==0){
        float b=0.f;
        for(int j=0;j<32;j++) b += swq[j]*spwv_b[j];
        g_beff[p]=b;
    }
}

// ================ K5: s-field ================
__global__ void __launch_bounds__(256) k_sfield(const float* __restrict__ ub, int khkw,
                                                size_t imgstride, int piBase,
                                                float* __restrict__ sf){
    __shared__ float Vs[64*65];
    __shared__ float part[4*64];
    __shared__ float ve[64];
    int q0 = blockIdx.x*64, bp = blockIdx.y, n = blockIdx.z;
    int t = threadIdx.x;
    int pi = piBase + n*gridDim.y + bp;
    const float* base = ub + (size_t)n*imgstride + (size_t)bp*64*khkw + q0;
    int qlim = khkw - q0; if(qlim>64) qlim=64;

    if(t<64) ve[t]=g_veff[pi*64+t];
    for(int i=t;i<4096;i+=256){
        int c=i>>6, j=i&63;
        Vs[c*65+j] = (j<qlim) ? base[(size_t)c*khkw + j] : 0.f;
    }
    __syncthreads();
    {
        int j=t&63, cg=t>>6;
        float s=0.f;
        #pragma unroll 4
        for(int cc=cg*16; cc<cg*16+16; cc++) s += ve[cc]*Vs[cc*65+j];
        part[cg*64+j]=s;
    }
    __syncthreads();
    if(t<64 && t<qlim){
        float sd = part[t]+part[64+t]+part[128+t]+part[192+t] + g_beff[pi];
        sf[(size_t)n*(gridDim.y*khkw) + (size_t)bp*khkw + q0 + t] = sigf(sd);
    }
}

// ================ K6: multiplier + fused output GEMM ================
__global__ void __launch_bounds__(256) k6(const float* __restrict__ x, float* __restrict__ out){
    __shared__ __align__(16) float exs[NO*PAD];
    __shared__ __align__(16) float xs[64*PAD];
    __shared__ int ncS[32], C0S[32], C1S[32];
    __shared__ int nrS, R0S, R1S;

    int t = threadIdx.x;
    int wt = blockIdx.x, h = blockIdx.y, n = blockIdx.z;
    int w0 = wt*32;

    const float* exg = g_ex + (size_t)n*NO*HW + (size_t)h*Wd + w0;
    for(int i=t;i<NO*32;i+=256){ int k=i>>5, pix=i&31; exs[k*PAD+pix]=exg[(size_t)k*HW+pix]; }
    const float* xp = x + (size_t)n*64*HW + (size_t)h*Wd + w0;
    for(int i=t;i<64*32;i+=256){ int c=i>>5, pix=i&31; xs[c*PAD+pix]=xp[(size_t)c*HW+pix]; }
    if(t==0){ int R[2]; int nr=cover3(h,R); nrS=nr; R0S=R[0]; R1S=(nr>1)?R[1]:R[0]; }
    if(t<32){ int C[2]; int nc=cover3(w0+t,C); ncS[t]=nc; C0S[t]=C[0]; C1S[t]=(nc>1)?C[1]:C[0]; }
    __syncthreads();

    int nr = nrS;
    // multiplier per (k, pix)
    for(int i=t;i<NO*32;i+=256){
        int k=i>>5, pix=i&31, win=k>>6, ci=k&63;
        int w = w0 + pix;
        float m;
        if(win==0){
            m = g_gt[n*64+ci] + g_sf1[n*HW + h*Wd + w];
        } else if(win==2){
            int p = (h>>5)*5 + (w>>5);
            int r = (h&31)*32 + (w&31);
            int G = ci*A5 + r*P5 + p;
            int bp = G>>16, mm = G&65535, cp = mm>>10, q = mm&1023;
            int pi = 160 + n*25 + bp;
            m = g_gt[pi*64+cp] + g_sf5[n*25600 + bp*1024 + q];
        } else {
            m = 0.f;
            int nc = ncS[pix];
            #pragma unroll
            for(int ri=0;ri<2;ri++){
                if(ri>=nr) break;
                int ph = (ri==0)?R0S:R1S;
                #pragma unroll
                for(int cj=0;cj<2;cj++){
                    if(cj>=nc) break;
                    int pw = (cj==0)?C0S[pix]:C1S[pix];
                    int p = ph*3+pw;
                    int r = (h-53*ph)*54 + (w-53*pw);
                    int G = ci*A3 + r*P3 + p;
                    int bp = G/B3, mm = G - bp*B3;
                    int cp = mm/KHKW3, q = mm - cp*KHKW3;
                    int pi = 16 + n*9 + bp;
                    m += g_gt[pi*64+cp] + g_sf3[n*26244 + bp*KHKW3 + q];
                }
            }
            m *= 1.f/(float)(nr*nc);
        }
        exs[k*PAD+pix] *= (1.f + m);
    }
    __syncthreads();

    // out = W2 @ ex' + F @ x + vb
    int ob = t&63, pg = t>>6, pb = pg*8;
    float vbv = g_vb[ob];
    u64 acc[4];
    #pragma unroll
    for(int j=0;j<4;j++) acc[j]=pk2(vbv,vbv);
    for(int k=0;k<NO;k++){
        float wv = g_W2t[k*64+ob];
        u64 wp = pk2(wv,wv);
        #pragma unroll
        for(int j=0;j<4;j++){ u64 ev=*(const u64*)&exs[k*PAD+pb+j*2]; fma2(acc[j],wp,ev); }
    }
    for(int c=0;c<64;c++){
        float fv = g_Ft[c*64+ob];
        u64 fp = pk2(fv,fv);
        #pragma unroll
        for(int j=0;j<4;j++){ u64 xv=*(const u64*)&xs[c*PAD+pb+j*2]; fma2(acc[j],fp,xv); }
    }
    __syncthreads();
    #pragma unroll
    for(int j=0;j<4;j++){
        float2 v=up2(acc[j]);
        xs[ob*PAD+pb+j*2  ]=v.x;
        xs[ob*PAD+pb+j*2+1]=v.y;
    }
    __syncthreads();
    float* og = out + (size_t)n*64*HW + (size_t)h*Wd + w0;
    for(int i=t;i<64*32;i+=256){ int o=i>>5, pix=i&31; og[(size_t)o*HW+pix]=xs[o*PAD+pix]; }
}

// ================ launch ================
extern "C" void kernel_launch(void* const* d_in, const int* in_sizes, int n_in,
                              void* d_out, int out_size){
    const float* x      = (const float*)d_in[0];
    const float* exp_w  = (const float*)d_in[1];
    const float* exp_b  = (const float*)d_in[2];
    const float* res_w  = (const float*)d_in[3];
    const float* res_b  = (const float*)d_in[4];
    const float* fus_w  = (const float*)d_in[5];
    const float* fus_b  = (const float*)d_in[6];
    const float* chwv_w = (const float*)d_in[7];
    const float* chwv_b = (const float*)d_in[8];
    const float* chwq_w = (const float*)d_in[9];
    const float* chwq_b = (const float*)d_in[10];
    const float* chwz_w = (const float*)d_in[11];
    const float* chwz_b = (const float*)d_in[12];
    const float* ln_g   = (const float*)d_in[13];
    const float* ln_b   = (const float*)d_in[14];
    const float* spwv_w = (const float*)d_in[15];
    const float* spwv_b = (const float*)d_in[16];
    const float* spwq_w = (const float*)d_in[17];
    const float* spwq_b = (const float*)d_in[18];
    float* out = (float*)d_out;

    float *g_ex_p, *g_u3_p, *g_u5_p;
    float *g_sf1_p, *g_sf3_p, *g_sf5_p;
    cudaGetSymbolAddress((void**)&g_ex_p, g_ex);
    cudaGetSymbolAddress((void**)&g_u3_p, g_u3);
    cudaGetSymbolAddress((void**)&g_u5_p, g_u5);
    cudaGetSymbolAddress((void**)&g_sf1_p, g_sf1);
    cudaGetSymbolAddress((void**)&g_sf3_p, g_sf3);
    cudaGetSymbolAddress((void**)&g_sf5_p, g_sf5);

    k_zero<<<(NPI*64+255)/256, 256>>>();
    k_wprep<<<1, 256>>>(exp_w, res_w, res_b, fus_w, fus_b);

    dim3 grid(Wd/32, Hh, NIMG);
    k1<<<grid, 256>>>(x, exp_b);

    k2_5<<<dim3(32,64,NIMG), 256>>>();
    k2_3<<<dim3(54,64,NIMG), 256>>>();

    // stats: win1 uses ex chunk0 directly (stride NO*HW per image)
    k_stats<<<dim3(HW/64, 1, NIMG), 256>>>(g_ex_p, HW,   (size_t)NO*HW, 0,   chwq_w, chwq_b);
    k_stats<<<dim3(46,    9, NIMG), 256>>>(g_u3_p, KHKW3,(size_t)U3IMG, 16,  chwq_w, chwq_b);
    k_stats<<<dim3(16,   25, NIMG), 256>>>(g_u5_p, KHKW5,(size_t)U5IMG, 160, chwq_w, chwq_b);

    k4<<<NPI, 64>>>(chwv_w, chwv_b, chwz_w, chwz_b, ln_g, ln_b,
                    spwq_w, spwq_b, spwv_w, spwv_b);

    k_sfield<<<dim3(HW/64, 1, NIMG), 256>>>(g_ex_p, HW,   (size_t)NO*HW, 0,   g_sf1_p);
    k_sfield<<<dim3(46,    9, NIMG), 256>>>(g_u3_p, KHKW3,(size_t)U3IMG, 16,  g_sf3_p);
    k_sfield<<<dim3(16,   25, NIMG), 256>>>(g_u5_p, KHKW5,(size_t)U5IMG, 160, g_sf5_p);

    k6<<<grid, 256>>>(x, out);
}

// round 3
// speedup vs baseline: 1.3886x; 1.3886x over previous
#include <cuda_runtime.h>
#include <math.h>

typedef unsigned long long u64;

#define NIMG 16
#define NO   192
#define Hh   160
#define Wd   160
#define HW   25600
#define PAD  36

#define KHKW3 2916
#define P3    9
#define A3    26244
#define B3    186624
#define U3IMG 1679616
#define KHKW5 1024
#define P5    25
#define A5    25600
#define U5IMG 1638400
#define NPI   560

// ---------------- scratch ----------------
__device__ float g_ex[(size_t)NIMG*NO*HW];
__device__ float g_u3[(size_t)NIMG*U3IMG];
__device__ float g_u5[(size_t)NIMG*U5IMG];
__device__ float g_sf1[NIMG*HW];
__device__ float g_sf3[NIMG*P3*KHKW3];
__device__ float g_sf5[NIMG*P5*KHKW5];
__device__ float g_Z[NPI], g_S[NPI*64], g_Pm[NPI*64];
__device__ float g_gt[NPI*64], g_veff[NPI*64], g_beff[NPI];
__device__ float g_W2t[NO*64], g_Ft[64*64], g_vb[64], g_expWt[64*NO];

// ---------------- helpers ----------------
__device__ __forceinline__ u64 pk2(float lo, float hi){
    u64 r; asm("mov.b64 %0,{%1,%2};":"=l"(r):"f"(lo),"f"(hi)); return r;
}
__device__ __forceinline__ void fma2(u64 &d, u64 a, u64 b){
    asm("fma.rn.f32x2 %0,%1,%2,%3;":"=l"(d):"l"(a),"l"(b),"l"(d));
}
__device__ __forceinline__ float2 up2(u64 v){
    float2 f; asm("mov.b64 {%0,%1},%2;":"=f"(f.x),"=f"(f.y):"l"(v)); return f;
}
__device__ __forceinline__ float sigf(float x){ return 1.f/(1.f+expf(-x)); }
__device__ __forceinline__ int cover3(int h, int* r){
    int n=0;
    #pragma unroll
    for(int i=0;i<3;i++){ int lo=53*i; if(h>=lo && h<=lo+53) r[n++]=i; }
    return n;
}

// ================ K0a: zero accumulators ================
__global__ void k_zero(){
    int i = blockIdx.x*256 + threadIdx.x;
    if(i < NPI) g_Z[i]=0.f;
    if(i < NPI*64){ g_S[i]=0.f; g_Pm[i]=0.f; }
}

// ================ K0b: weight prep ================
__global__ void k_wprep(const float* __restrict__ exp_w, const float* __restrict__ res_w,
                        const float* __restrict__ res_b, const float* __restrict__ fus_w,
                        const float* __restrict__ fus_b){
    int t = threadIdx.x;
    for(int i=t;i<64*NO;i+=256){ int c=i/NO, o=i%NO; g_expWt[i]=exp_w[o*64+c]; }
    for(int i=t;i<64*64;i+=256){ int c=i/64, o=i%64; g_Ft[i]=fus_w[o*64+c]; }
    for(int i=t;i<NO*64;i+=256){
        int k=i/64, o=i%64; float s=0.f;
        for(int c=0;c<64;c++) s += fus_w[o*64+c]*res_w[c*NO+k];
        g_W2t[i]=s;
    }
    for(int o=t;o<64;o+=256){
        float s=fus_b[o];
        for(int c=0;c<64;c++) s += fus_w[o*64+c]*res_b[c];
        g_vb[o]=s;
    }
}

// ================ K1: ex = Wexp @ x ================
__global__ void __launch_bounds__(256) k1(const float* __restrict__ x,
                                          const float* __restrict__ exp_b){
    __shared__ __align__(16) float xs[64*PAD];
    int t = threadIdx.x;
    int wt = blockIdx.x, h = blockIdx.y, n = blockIdx.z;
    int w0 = wt*32;

    const float* xp = x + (size_t)n*64*HW + (size_t)h*Wd + w0;
    for(int i=t;i<512;i+=256){
        int c=i>>3, grp=(i&7)*4;
        *(float4*)&xs[c*PAD+grp] = *(const float4*)&xp[(size_t)c*HW+grp];
    }
    __syncthreads();

    int ob = t&63, pg = t>>6, pb = pg*8;
    u64 acc[3][4];
    #pragma unroll
    for(int a=0;a<3;a++)
        #pragma unroll
        for(int j=0;j<4;j++) acc[a][j]=0ull;
    for(int c=0;c<64;c++){
        u64 xv[4];
        #pragma unroll
        for(int j=0;j<4;j++) xv[j]=*(const u64*)&xs[c*PAD+pb+j*2];
        #pragma unroll
        for(int a=0;a<3;a++){
            float w = g_expWt[c*NO + ob + a*64];
            u64 wp = pk2(w,w);
            #pragma unroll
            for(int j=0;j<4;j++) fma2(acc[a][j], wp, xv[j]);
        }
    }
    float* exg = g_ex + (size_t)n*NO*HW + (size_t)h*Wd + w0;
    #pragma unroll
    for(int a=0;a<3;a++){
        float b = exp_b[ob+a*64];
        #pragma unroll
        for(int j=0;j<4;j++){
            float2 v = up2(acc[a][j]);
            *(float2*)&exg[(size_t)(ob+a*64)*HW + pb + j*2] = make_float2(v.x+b, v.y+b);
        }
    }
}

// ================ K2: repack into unfold order (warp-per-ci) ================
// win5: u5[n][(ci*1024 + y*32 + xx)*25 + p], p = ph*5+pw, src pixel (ph*32+y, pw*32+xx)
__global__ void __launch_bounds__(256) k2_5(){
    __shared__ __align__(16) float rb[8][800];
    int y = blockIdx.x, n = blockIdx.y;
    int wp = threadIdx.x >> 5, lane = threadIdx.x & 31;
    for(int cit=0; cit<8; cit++){
        int ci = cit*8 + wp;
        const float* src = g_ex + (size_t)n*NO*HW + (size_t)(128+ci)*HW;
        #pragma unroll
        for(int ph=0; ph<5; ph++){
            const float* row = src + (size_t)(ph*32+y)*Wd;
            #pragma unroll
            for(int it=0; it<5; it++){
                int w = lane + it*32;          // xx = lane, pw = it
                rb[wp][lane*25 + ph*5 + it] = row[w];
            }
        }
        __syncwarp();
        float4* dst = (float4*)(g_u5 + (size_t)n*U5IMG + (size_t)(ci*1024 + y*32)*25);
        const float4* srb = (const float4*)rb[wp];
        #pragma unroll
        for(int it=0; it<7; it++){
            int k = lane + it*32;
            if(k < 200) dst[k] = srb[k];
        }
        __syncwarp();
    }
}
// win3: u3[n][(ci*2916 + yy*54 + xx)*9 + p], p = ph*3+pw, src pixel (53*ph+yy, 53*pw+xx)
__global__ void __launch_bounds__(256) k2_3(){
    __shared__ __align__(16) float rb[8][486];
    int yy = blockIdx.x, n = blockIdx.y;
    int wp = threadIdx.x >> 5, lane = threadIdx.x & 31;
    for(int cit=0; cit<8; cit++){
        int ci = cit*8 + wp;
        const float* src = g_ex + (size_t)n*NO*HW + (size_t)(64+ci)*HW;
        #pragma unroll
        for(int ph=0; ph<3; ph++){
            const float* row = src + (size_t)(53*ph+yy)*Wd;
            #pragma unroll
            for(int it=0; it<5; it++){
                int w = lane + it*32;
                float v = row[w];
                #pragma unroll
                for(int pw=0; pw<3; pw++){
                    int xx = w - 53*pw;
                    if(xx>=0 && xx<54) rb[wp][xx*9 + ph*3 + pw] = v;
                }
            }
        }
        __syncwarp();
        float2* dst = (float2*)(g_u3 + (size_t)n*U3IMG + (size_t)ci*A3 + (size_t)yy*486);
        const float2* srb = (const float2*)rb[wp];
        #pragma unroll
        for(int it=0; it<8; it++){
            int k = lane + it*32;
            if(k < 243) dst[k] = srb[k];
        }
        __syncwarp();
    }
}

// ================ K3: pseudo-image stats (Z, S, Pm), q-tile = 128 ================
__global__ void __launch_bounds__(256) k_stats(const float* __restrict__ ub, int khkw,
                                               size_t imgstride, int piBase,
                                               const float* __restrict__ wq,
                                               const float* __restrict__ wqb){
    __shared__ float Vs[64*129];
    __shared__ float part[2*128];
    __shared__ float es[128];
    int q0 = blockIdx.x*128, bp = blockIdx.y, n = blockIdx.z;
    int t = threadIdx.x;
    const float* base = ub + (size_t)n*imgstride + (size_t)bp*64*khkw + q0;
    int qlim = khkw - q0; if(qlim>128) qlim=128;

    for(int i=t;i<2048;i+=256){
        int c=i>>5, j4=(i&31)*4;
        float4 v = (j4<qlim) ? *(const float4*)&base[(size_t)c*khkw + j4]
                             : make_float4(0.f,0.f,0.f,0.f);
        float* vp = &Vs[c*129+j4];
        vp[0]=v.x; vp[1]=v.y; vp[2]=v.z; vp[3]=v.w;
    }
    __syncthreads();
    { // qdot partials: 2 cc-groups x 128 j
        int j=t&127, cg=t>>7;
        float s=0.f;
        #pragma unroll 8
        for(int cc=cg*32; cc<cg*32+32; cc++) s += wq[cc]*Vs[cc*129+j];
        part[cg*128+j]=s;
    }
    __syncthreads();
    int pi = piBase + n*gridDim.y + bp;
    if(t<128){
        float qd = part[t]+part[128+t] + wqb[0];
        float e = (t<qlim) ? expf(qd) : 0.f;
        es[t]=e;
        float z=e;
        for(int off=16;off;off>>=1) z += __shfl_xor_sync(0xffffffffu,z,off);
        if((t&31)==0) atomicAdd(&g_Z[pi], z);
    }
    __syncthreads();
    { // S, Pm partials: 64 c x 4 j-groups
        int c=t&63, jg=t>>6;
        float ss=0.f, pm=0.f;
        #pragma unroll 8
        for(int jj=jg*32; jj<jg*32+32; jj++){ float v=Vs[c*129+jj]; ss += v*es[jj]; pm += v; }
        atomicAdd(&g_S[pi*64+c], ss);
        atomicAdd(&g_Pm[pi*64+c], pm);
    }
}

// ================ K4: per-pseudo-image finalize ================
__global__ void __launch_bounds__(64) k4(const float* __restrict__ chwv_w, const float* __restrict__ chwv_b,
                                         const float* __restrict__ chwz_w, const float* __restrict__ chwz_b,
                                         const float* __restrict__ ln_g,  const float* __restrict__ ln_b,
                                         const float* __restrict__ spwq_w,const float* __restrict__ spwq_b,
                                         const float* __restrict__ spwv_w,const float* __restrict__ spwv_b){
    int p = blockIdx.x, t = threadIdx.x;
    float hw = (p<16) ? 25600.f : ((p<160) ? 2916.f : 1024.f);
    __shared__ float xbar[64], pmean[64], wz[32], red[64], swq[32];

    float Zinv = 1.f/g_Z[p];
    xbar[t]  = g_S[p*64+t]*Zinv;
    pmean[t] = g_Pm[p*64+t]/hw;
    __syncthreads();

    if(t<32){
        float s = chwv_b[t];
        for(int c=0;c<64;c++) s += chwv_w[t*64+c]*xbar[c];
        wz[t]=s;
    }
    __syncthreads();

    float z = chwz_b[t];
    for(int j=0;j<32;j++) z += chwz_w[t*32+j]*wz[j];

    red[t]=z; __syncthreads();
    for(int s=32;s>0;s>>=1){ if(t<s) red[t]+=red[t+s]; __syncthreads(); }
    float mu = red[0]*(1.f/64.f); __syncthreads();
    float d = z-mu;
    red[t]=d*d; __syncthreads();
    for(int s=32;s>0;s>>=1){ if(t<s) red[t]+=red[t+s]; __syncthreads(); }
    float var = red[0]*(1.f/64.f);

    float zn = d*rsqrtf(var+1e-5f)*ln_g[t] + ln_b[t];
    g_gt[p*64+t] = sigf(zn);
    __syncthreads();

    if(t<32){
        float s = spwq_b[t];
        for(int c=0;c<64;c++) s += spwq_w[t*64+c]*pmean[c];
        float m=s;
        for(int off=16;off;off>>=1) m=fmaxf(m,__shfl_xor_sync(0xffffffffu,m,off));
        float e=expf(s-m), sum=e;
        for(int off=16;off;off>>=1) sum+=__shfl_xor_sync(0xffffffffu,sum,off);
        swq[t]=e/sum;
    }
    __syncthreads();

    float v=0.f;
    for(int j=0;j<32;j++) v += swq[j]*spwv_w[j*64+t];
    g_veff[p*64+t]=v;
    if(t==0){
        float b=0.f;
        for(int j=0;j<32;j++) b += swq[j]*spwv_b[j];
        g_beff[p]=b;
    }
}

// ================ K5: s-field, q-tile = 128 ================
__global__ void __launch_bounds__(256) k_sfield(const float* __restrict__ ub, int khkw,
                                                size_t imgstride, int piBase,
                                                float* __restrict__ sf){
    __shared__ float Vs[64*129];
    __shared__ float part[2*128];
    __shared__ float ve[64];
    int q0 = blockIdx.x*128, bp = blockIdx.y, n = blockIdx.z;
    int t = threadIdx.x;
    int pi = piBase + n*gridDim.y + bp;
    const float* base = ub + (size_t)n*imgstride + (size_t)bp*64*khkw + q0;
    int qlim = khkw - q0; if(qlim>128) qlim=128;

    if(t<64) ve[t]=g_veff[pi*64+t];
    for(int i=t;i<2048;i+=256){
        int c=i>>5, j4=(i&31)*4;
        float4 v = (j4<qlim) ? *(const float4*)&base[(size_t)c*khkw + j4]
                             : make_float4(0.f,0.f,0.f,0.f);
        float* vp = &Vs[c*129+j4];
        vp[0]=v.x; vp[1]=v.y; vp[2]=v.z; vp[3]=v.w;
    }
    __syncthreads();
    {
        int j=t&127, cg=t>>7;
        float s=0.f;
        #pragma unroll 8
        for(int cc=cg*32; cc<cg*32+32; cc++) s += ve[cc]*Vs[cc*129+j];
        part[cg*128+j]=s;
    }
    __syncthreads();
    if(t<128 && t<qlim){
        float sd = part[t]+part[128+t] + g_beff[pi];
        sf[(size_t)n*(gridDim.y*khkw) + (size_t)bp*khkw + q0 + t] = sigf(sd);
    }
}

// ================ K6: multiplier + fused output GEMM ================
__global__ void __launch_bounds__(256) k6(const float* __restrict__ x, float* __restrict__ out){
    __shared__ __align__(16) float exs[NO*PAD];
    __shared__ __align__(16) float xs[64*PAD];
    __shared__ int ncS[32], C0S[32], C1S[32];
    __shared__ int nrS, R0S, R1S;

    int t = threadIdx.x;
    int wt = blockIdx.x, h = blockIdx.y, n = blockIdx.z;
    int w0 = wt*32;

    const float* exg = g_ex + (size_t)n*NO*HW + (size_t)h*Wd + w0;
    for(int i=t;i<1536;i+=256){
        int k=i>>3, grp=(i&7)*4;
        *(float4*)&exs[k*PAD+grp] = *(const float4*)&exg[(size_t)k*HW+grp];
    }
    const float* xp = x + (size_t)n*64*HW + (size_t)h*Wd + w0;
    for(int i=t;i<512;i+=256){
        int c=i>>3, grp=(i&7)*4;
        *(float4*)&xs[c*PAD+grp] = *(const float4*)&xp[(size_t)c*HW+grp];
    }
    if(t==0){ int R[2]; int nr=cover3(h,R); nrS=nr; R0S=R[0]; R1S=(nr>1)?R[1]:R[0]; }
    if(t<32){ int C[2]; int nc=cover3(w0+t,C); ncS[t]=nc; C0S[t]=C[0]; C1S[t]=(nc>1)?C[1]:C[0]; }
    __syncthreads();

    int nr = nrS;
    for(int i=t;i<NO*32;i+=256){
        int k=i>>5, pix=i&31, win=k>>6, ci=k&63;
        int w = w0 + pix;
        float m;
        if(win==0){
            m = g_gt[n*64+ci] + g_sf1[n*HW + h*Wd + w];
        } else if(win==2){
            int p = (h>>5)*5 + (w>>5);
            int r = (h&31)*32 + (w&31);
            int G = ci*A5 + r*P5 + p;
            int bp = G>>16, mm = G&65535, cp = mm>>10, q = mm&1023;
            int pi = 160 + n*25 + bp;
            m = g_gt[pi*64+cp] + g_sf5[n*25600 + bp*1024 + q];
        } else {
            m = 0.f;
            int nc = ncS[pix];
            #pragma unroll
            for(int ri=0;ri<2;ri++){
                if(ri>=nr) break;
                int ph = (ri==0)?R0S:R1S;
                #pragma unroll
                for(int cj=0;cj<2;cj++){
                    if(cj>=nc) break;
                    int pw = (cj==0)?C0S[pix]:C1S[pix];
                    int p = ph*3+pw;
                    int r = (h-53*ph)*54 + (w-53*pw);
                    int G = ci*A3 + r*P3 + p;
                    int bp = G/B3, mm = G - bp*B3;
                    int cp = mm/KHKW3, q = mm - cp*KHKW3;
                    int pi = 16 + n*9 + bp;
                    m += g_gt[pi*64+cp] + g_sf3[n*26244 + bp*KHKW3 + q];
                }
            }
            m *= 1.f/(float)(nr*nc);
        }
        exs[k*PAD+pix] *= (1.f + m);
    }
    __syncthreads();

    int ob = t&63, pg = t>>6, pb = pg*8;
    float vbv = g_vb[ob];
    u64 acc[4];
    #pragma unroll
    for(int j=0;j<4;j++) acc[j]=pk2(vbv,vbv);
    for(int k=0;k<NO;k++){
        float wv = g_W2t[k*64+ob];
        u64 wp = pk2(wv,wv);
        #pragma unroll
        for(int j=0;j<4;j++){ u64 ev=*(const u64*)&exs[k*PAD+pb+j*2]; fma2(acc[j],wp,ev); }
    }
    for(int c=0;c<64;c++){
        float fv = g_Ft[c*64+ob];
        u64 fp = pk2(fv,fv);
        #pragma unroll
        for(int j=0;j<4;j++){ u64 xv=*(const u64*)&xs[c*PAD+pb+j*2]; fma2(acc[j],fp,xv); }
    }
    __syncthreads();
    #pragma unroll
    for(int j=0;j<4;j++){
        float2 v=up2(acc[j]);
        xs[ob*PAD+pb+j*2  ]=v.x;
        xs[ob*PAD+pb+j*2+1]=v.y;
    }
    __syncthreads();
    float* og = out + (size_t)n*64*HW + (size_t)h*Wd + w0;
    for(int i=t;i<512;i+=256){
        int o=i>>3, grp=(i&7)*4;
        *(float4*)&og[(size_t)o*HW+grp] = *(const float4*)&xs[o*PAD+grp];
    }
}

// ================ launch ================
extern "C" void kernel_launch(void* const* d_in, const int* in_sizes, int n_in,
                              void* d_out, int out_size){
    const float* x      = (const float*)d_in[0];
    const float* exp_w  = (const float*)d_in[1];
    const float* exp_b  = (const float*)d_in[2];
    const float* res_w  = (const float*)d_in[3];
    const float* res_b  = (const float*)d_in[4];
    const float* fus_w  = (const float*)d_in[5];
    const float* fus_b  = (const float*)d_in[6];
    const float* chwv_w = (const float*)d_in[7];
    const float* chwv_b = (const float*)d_in[8];
    const float* chwq_w = (const float*)d_in[9];
    const float* chwq_b = (const float*)d_in[10];
    const float* chwz_w = (const float*)d_in[11];
    const float* chwz_b = (const float*)d_in[12];
    const float* ln_g   = (const float*)d_in[13];
    const float* ln_b   = (const float*)d_in[14];
    const float* spwv_w = (const float*)d_in[15];
    const float* spwv_b = (const float*)d_in[16];
    const float* spwq_w = (const float*)d_in[17];
    const float* spwq_b = (const float*)d_in[18];
    float* out = (float*)d_out;

    float *g_ex_p, *g_u3_p, *g_u5_p;
    float *g_sf1_p, *g_sf3_p, *g_sf5_p;
    cudaGetSymbolAddress((void**)&g_ex_p, g_ex);
    cudaGetSymbolAddress((void**)&g_u3_p, g_u3);
    cudaGetSymbolAddress((void**)&g_u5_p, g_u5);
    cudaGetSymbolAddress((void**)&g_sf1_p, g_sf1);
    cudaGetSymbolAddress((void**)&g_sf3_p, g_sf3);
    cudaGetSymbolAddress((void**)&g_sf5_p, g_sf5);

    k_zero<<<(NPI*64+255)/256, 256>>>();
    k_wprep<<<1, 256>>>(exp_w, res_w, res_b, fus_w, fus_b);

    dim3 grid(Wd/32, Hh, NIMG);
    k1<<<grid, 256>>>(x, exp_b);

    k2_5<<<dim3(32,NIMG), 256>>>();
    k2_3<<<dim3(54,NIMG), 256>>>();

    k_stats<<<dim3(200, 1, NIMG), 256>>>(g_ex_p, HW,   (size_t)NO*HW, 0,   chwq_w, chwq_b);
    k_stats<<<dim3(23,  9, NIMG), 256>>>(g_u3_p, KHKW3,(size_t)U3IMG, 16,  chwq_w, chwq_b);
    k_stats<<<dim3(8,  25, NIMG), 256>>>(g_u5_p, KHKW5,(size_t)U5IMG, 160, chwq_w, chwq_b);

    k4<<<NPI, 64>>>(chwv_w, chwv_b, chwz_w, chwz_b, ln_g, ln_b,
                    spwq_w, spwq_b, spwv_w, spwv_b);

    k_sfield<<<dim3(200, 1, NIMG), 256>>>(g_ex_p, HW,   (size_t)NO*HW, 0,   g_sf1_p);
    k_sfield<<<dim3(23,  9, NIMG), 256>>>(g_u3_p, KHKW3,(size_t)U3IMG, 16,  g_sf3_p);
    k_sfield<<<dim3(8,  25, NIMG), 256>>>(g_u5_p, KHKW5,(size_t)U5IMG, 160, g_sf5_p);

    k6<<<grid, 256>>>(x, out);
}